// round 6
// baseline (speedup 1.0000x reference)
#include <cuda_runtime.h>

// RegionIntegrator: fixed geometry
//   B=4, N_REG=225 (15x15 grid, step 32), C=16, RS=64, H=W=512, pad=0.
// Gather formulation: each output pixel (i,j) is covered by at most 2x2
// regions whose starts are multiples of 32 in [p-63, p] clamped to [0,448].
// Coverage set is constant within each aligned 32-px span per axis, so an
// even/odd row pair (i, i+1) shares the same region set and count.
// R6 = R2 (two rows per thread: 2x index amortization, 8 LDG.128 in flight)
//    + R4's streaming store hint (__stcs; output never re-read).

#define RI_B   4
#define RI_N   225
#define RI_C   16
#define RI_HW  512
#define RI_W4  128  // 512 / 4
#define RI_H2  256  // 512 / 2 row-pairs

__global__ __launch_bounds__(256) void region_gather2s_kernel(
    const float* __restrict__ regions, float* __restrict__ out)
{
    int idx = blockIdx.x * blockDim.x + threadIdx.x;   // over B*C*(H/2)*(W/4) = 2,097,152
    int j4 = (idx & (RI_W4 - 1)) << 2;                 // 0..508, multiple of 4
    int i  = ((idx >> 7) & (RI_H2 - 1)) << 1;          // even row 0..510
    int bc = idx >> 15;                                 // b*16 + c
    int c  = bc & (RI_C - 1);
    int b  = bc >> 4;

    // Covering row starts: multiples of 32 in [max(0,i-63), min(448,i)].
    // Same set for rows i and i+1 (pair never straddles a 32-boundary).
    int lo_i       = i - 63; if (lo_i < 0) lo_i = 0;
    int hi_i       = i < 448 ? i : 448;
    int s_first_i  = ((lo_i + 31) >> 5) << 5;
    int s_last_i   = (hi_i >> 5) << 5;

    int lo_j       = j4 - 63; if (lo_j < 0) lo_j = 0;
    int hi_j       = j4 < 448 ? j4 : 448;
    int s_first_j  = ((lo_j + 31) >> 5) << 5;
    int s_last_j   = (hi_j >> 5) << 5;

    bool two_i = (s_last_i != s_first_i);
    bool two_j = (s_last_j != s_first_j);

    // regions[((b*225 + n)*16 + c) * 4096 + ri*64 + rj]
    long base_bc = ((long)b * RI_N) * RI_C + c;

    float4 a0 = make_float4(0.f, 0.f, 0.f, 0.f);   // row i
    float4 a1 = make_float4(0.f, 0.f, 0.f, 0.f);   // row i+1

    {
        int n  = (s_first_i >> 5) * 15 + (s_first_j >> 5);
        long off = (base_bc + (long)n * RI_C) * 4096 + ((i - s_first_i) << 6) + (j4 - s_first_j);
        float4 v0 = *reinterpret_cast<const float4*>(regions + off);
        float4 v1 = *reinterpret_cast<const float4*>(regions + off + 64);
        a0.x += v0.x; a0.y += v0.y; a0.z += v0.z; a0.w += v0.w;
        a1.x += v1.x; a1.y += v1.y; a1.z += v1.z; a1.w += v1.w;
    }
    if (two_j) {
        int n  = (s_first_i >> 5) * 15 + (s_last_j >> 5);
        long off = (base_bc + (long)n * RI_C) * 4096 + ((i - s_first_i) << 6) + (j4 - s_last_j);
        float4 v0 = *reinterpret_cast<const float4*>(regions + off);
        float4 v1 = *reinterpret_cast<const float4*>(regions + off + 64);
        a0.x += v0.x; a0.y += v0.y; a0.z += v0.z; a0.w += v0.w;
        a1.x += v1.x; a1.y += v1.y; a1.z += v1.z; a1.w += v1.w;
    }
    if (two_i) {
        int n  = (s_last_i >> 5) * 15 + (s_first_j >> 5);
        long off = (base_bc + (long)n * RI_C) * 4096 + ((i - s_last_i) << 6) + (j4 - s_first_j);
        float4 v0 = *reinterpret_cast<const float4*>(regions + off);
        float4 v1 = *reinterpret_cast<const float4*>(regions + off + 64);
        a0.x += v0.x; a0.y += v0.y; a0.z += v0.z; a0.w += v0.w;
        a1.x += v1.x; a1.y += v1.y; a1.z += v1.z; a1.w += v1.w;
    }
    if (two_i && two_j) {
        int n  = (s_last_i >> 5) * 15 + (s_last_j >> 5);
        long off = (base_bc + (long)n * RI_C) * 4096 + ((i - s_last_i) << 6) + (j4 - s_last_j);
        float4 v0 = *reinterpret_cast<const float4*>(regions + off);
        float4 v1 = *reinterpret_cast<const float4*>(regions + off + 64);
        a0.x += v0.x; a0.y += v0.y; a0.z += v0.z; a0.w += v0.w;
        a1.x += v1.x; a1.y += v1.y; a1.z += v1.z; a1.w += v1.w;
    }

    int cnt = (two_i ? 2 : 1) * (two_j ? 2 : 1);   // 1, 2 or 4
    float inv = (cnt == 1) ? 1.0f : (cnt == 2 ? 0.5f : 0.25f);
    a0.x *= inv; a0.y *= inv; a0.z *= inv; a0.w *= inv;
    a1.x *= inv; a1.y *= inv; a1.z *= inv; a1.w *= inv;

    long oidx = ((long)bc * RI_HW + i) * RI_HW + j4;
    __stcs(reinterpret_cast<float4*>(out + oidx), a0);
    __stcs(reinterpret_cast<float4*>(out + oidx + RI_HW), a1);
}

extern "C" void kernel_launch(void* const* d_in, const int* in_sizes, int n_in,
                              void* d_out, int out_size)
{
    const float* regions = (const float*)d_in[0];
    float* out = (float*)d_out;
    int total = RI_B * RI_C * RI_H2 * RI_W4;   // 2,097,152
    int block = 256;
    int grid = total / block;                  // 8192
    region_gather2s_kernel<<<grid, block>>>(regions, out);
}

// round 7
// speedup vs baseline: 1.0078x; 1.0078x over previous
#include <cuda_runtime.h>

// RegionIntegrator: fixed geometry
//   B=4, N_REG=225 (15x15 grid, step 32), C=16, RS=64, H=W=512, pad=0.
// Gather formulation (R4 shape — best: 43.5us ncu, DRAM 82.0%): each output
// pixel (i,j) is covered by at most 2x2 regions whose starts are multiples
// of 32 in [p-63, p] clamped to [0,448]. Count in {1,2,4} -> exact
// reciprocal. Store uses streaming hint (__stcs; output never re-read).
// R7 delta: block 256 -> 512 (launch-shape only; kernel body identical).

#define RI_B   4
#define RI_N   225
#define RI_C   16
#define RI_HW  512
#define RI_W4  128  // 512 / 4

__global__ __launch_bounds__(512) void region_gather_kernel(
    const float* __restrict__ regions, float* __restrict__ out)
{
    int idx = blockIdx.x * blockDim.x + threadIdx.x;   // over B*C*H*(W/4) = 4,194,304
    int j4 = (idx & (RI_W4 - 1)) << 2;                 // 0..508, multiple of 4
    int i  = (idx >> 7) & (RI_HW - 1);                 // 0..511
    int bc = idx >> 16;                                 // b*16 + c
    int c  = bc & (RI_C - 1);
    int b  = bc >> 4;

    // Covering row starts: multiples of 32 in [max(0,i-63), min(448,i)]
    int lo_i       = i - 63; if (lo_i < 0) lo_i = 0;
    int hi_i       = i < 448 ? i : 448;
    int s_first_i  = ((lo_i + 31) >> 5) << 5;
    int s_last_i   = (hi_i >> 5) << 5;

    int lo_j       = j4 - 63; if (lo_j < 0) lo_j = 0;
    int hi_j       = j4 < 448 ? j4 : 448;
    int s_first_j  = ((lo_j + 31) >> 5) << 5;
    int s_last_j   = (hi_j >> 5) << 5;

    bool two_i = (s_last_i != s_first_i);
    bool two_j = (s_last_j != s_first_j);

    // regions[((b*225 + n)*16 + c) * 4096 + ri*64 + rj]
    long base_bc = ((long)b * RI_N) * RI_C + c;

    float4 acc = make_float4(0.f, 0.f, 0.f, 0.f);

    {
        int n  = (s_first_i >> 5) * 15 + (s_first_j >> 5);
        long off = (base_bc + (long)n * RI_C) * 4096 + ((i - s_first_i) << 6) + (j4 - s_first_j);
        float4 v = *reinterpret_cast<const float4*>(regions + off);
        acc.x += v.x; acc.y += v.y; acc.z += v.z; acc.w += v.w;
    }
    if (two_j) {
        int n  = (s_first_i >> 5) * 15 + (s_last_j >> 5);
        long off = (base_bc + (long)n * RI_C) * 4096 + ((i - s_first_i) << 6) + (j4 - s_last_j);
        float4 v = *reinterpret_cast<const float4*>(regions + off);
        acc.x += v.x; acc.y += v.y; acc.z += v.z; acc.w += v.w;
    }
    if (two_i) {
        int n  = (s_last_i >> 5) * 15 + (s_first_j >> 5);
        long off = (base_bc + (long)n * RI_C) * 4096 + ((i - s_last_i) << 6) + (j4 - s_first_j);
        float4 v = *reinterpret_cast<const float4*>(regions + off);
        acc.x += v.x; acc.y += v.y; acc.z += v.z; acc.w += v.w;
    }
    if (two_i && two_j) {
        int n  = (s_last_i >> 5) * 15 + (s_last_j >> 5);
        long off = (base_bc + (long)n * RI_C) * 4096 + ((i - s_last_i) << 6) + (j4 - s_last_j);
        float4 v = *reinterpret_cast<const float4*>(regions + off);
        acc.x += v.x; acc.y += v.y; acc.z += v.z; acc.w += v.w;
    }

    int cnt = (two_i ? 2 : 1) * (two_j ? 2 : 1);   // 1, 2 or 4
    float inv = (cnt == 1) ? 1.0f : (cnt == 2 ? 0.5f : 0.25f);
    acc.x *= inv; acc.y *= inv; acc.z *= inv; acc.w *= inv;

    long oidx = ((long)bc * RI_HW + i) * RI_HW + j4;
    __stcs(reinterpret_cast<float4*>(out + oidx), acc);
}

extern "C" void kernel_launch(void* const* d_in, const int* in_sizes, int n_in,
                              void* d_out, int out_size)
{
    const float* regions = (const float*)d_in[0];
    float* out = (float*)d_out;
    int total = RI_B * RI_C * RI_HW * RI_W4;   // 4,194,304
    int block = 512;
    int grid = total / block;                  // 8192
    region_gather_kernel<<<grid, block>>>(regions, out);
}

// round 10
// speedup vs baseline: 1.0423x; 1.0343x over previous
#include <cuda_runtime.h>

// RegionIntegrator — FINAL (R4 shape; best measured: 43.5us ncu, DRAM 82.0%,
// 6.49 TB/s, bench 49.15us, rel_err 0).
//
// Fixed geometry: B=4, N_REG=225 (15x15 grid, step 32), C=16, RS=64,
// H=W=512, pad=0. The reference's scatter-add + coverage-count division is
// inverted into a pure gather: each output pixel (i,j) is covered by at
// most 2x2 regions, whose starts are the multiples of 32 in [p-63, p]
// clamped to [0,448] per axis. Coverage count = (#row starts)*(#col starts)
// in {1,2,4} -> exact fp32 reciprocal. No atomics, no count buffer, orig_x
// unused. Each input byte is read exactly once; traffic is minimal
// (236 MB read + 67 MB write).
//
// Tuning outcomes baked in:
//  - 1 float4 quad per thread (a 4-aligned quad never straddles a region
//    edge, so vectorization is exact); block=256. Row-pairing and block=512
//    both measured slower (cross-CTA L1tex-queue spread at higher MLP).
//  - Default caching on loads (__ldcs measured -5% DRAM busy).
//  - Streaming store __stcs (output never re-read): +2.8% DRAM busy, -1.8us.

#define RI_B   4
#define RI_N   225
#define RI_C   16
#define RI_HW  512
#define RI_W4  128  // 512 / 4

__global__ __launch_bounds__(256) void region_gather_kernel(
    const float* __restrict__ regions, float* __restrict__ out)
{
    int idx = blockIdx.x * blockDim.x + threadIdx.x;   // over B*C*H*(W/4) = 4,194,304
    int j4 = (idx & (RI_W4 - 1)) << 2;                 // 0..508, multiple of 4
    int i  = (idx >> 7) & (RI_HW - 1);                 // 0..511
    int bc = idx >> 16;                                 // b*16 + c
    int c  = bc & (RI_C - 1);
    int b  = bc >> 4;

    // Covering row starts: multiples of 32 in [max(0,i-63), min(448,i)]
    int lo_i       = i - 63; if (lo_i < 0) lo_i = 0;
    int hi_i       = i < 448 ? i : 448;
    int s_first_i  = ((lo_i + 31) >> 5) << 5;
    int s_last_i   = (hi_i >> 5) << 5;

    int lo_j       = j4 - 63; if (lo_j < 0) lo_j = 0;
    int hi_j       = j4 < 448 ? j4 : 448;
    int s_first_j  = ((lo_j + 31) >> 5) << 5;
    int s_last_j   = (hi_j >> 5) << 5;

    bool two_i = (s_last_i != s_first_i);
    bool two_j = (s_last_j != s_first_j);

    // regions[((b*225 + n)*16 + c) * 4096 + ri*64 + rj]
    long base_bc = ((long)b * RI_N) * RI_C + c;

    float4 acc = make_float4(0.f, 0.f, 0.f, 0.f);

    {
        int n  = (s_first_i >> 5) * 15 + (s_first_j >> 5);
        long off = (base_bc + (long)n * RI_C) * 4096 + ((i - s_first_i) << 6) + (j4 - s_first_j);
        float4 v = *reinterpret_cast<const float4*>(regions + off);
        acc.x += v.x; acc.y += v.y; acc.z += v.z; acc.w += v.w;
    }
    if (two_j) {
        int n  = (s_first_i >> 5) * 15 + (s_last_j >> 5);
        long off = (base_bc + (long)n * RI_C) * 4096 + ((i - s_first_i) << 6) + (j4 - s_last_j);
        float4 v = *reinterpret_cast<const float4*>(regions + off);
        acc.x += v.x; acc.y += v.y; acc.z += v.z; acc.w += v.w;
    }
    if (two_i) {
        int n  = (s_last_i >> 5) * 15 + (s_first_j >> 5);
        long off = (base_bc + (long)n * RI_C) * 4096 + ((i - s_last_i) << 6) + (j4 - s_first_j);
        float4 v = *reinterpret_cast<const float4*>(regions + off);
        acc.x += v.x; acc.y += v.y; acc.z += v.z; acc.w += v.w;
    }
    if (two_i && two_j) {
        int n  = (s_last_i >> 5) * 15 + (s_last_j >> 5);
        long off = (base_bc + (long)n * RI_C) * 4096 + ((i - s_last_i) << 6) + (j4 - s_last_j);
        float4 v = *reinterpret_cast<const float4*>(regions + off);
        acc.x += v.x; acc.y += v.y; acc.z += v.z; acc.w += v.w;
    }

    int cnt = (two_i ? 2 : 1) * (two_j ? 2 : 1);   // 1, 2 or 4
    float inv = (cnt == 1) ? 1.0f : (cnt == 2 ? 0.5f : 0.25f);
    acc.x *= inv; acc.y *= inv; acc.z *= inv; acc.w *= inv;

    long oidx = ((long)bc * RI_HW + i) * RI_HW + j4;
    __stcs(reinterpret_cast<float4*>(out + oidx), acc);
}

extern "C" void kernel_launch(void* const* d_in, const int* in_sizes, int n_in,
                              void* d_out, int out_size)
{
    const float* regions = (const float*)d_in[0];
    float* out = (float*)d_out;
    int total = RI_B * RI_C * RI_HW * RI_W4;   // 4,194,304
    int block = 256;
    int grid = total / block;                  // 16384
    region_gather_kernel<<<grid, block>>>(regions, out);
}

// round 11
// speedup vs baseline: 1.0430x; 1.0007x over previous
#include <cuda_runtime.h>

// RegionIntegrator: fixed geometry
//   B=4, N_REG=225 (15x15 grid, step 32), C=16, RS=64, H=W=512, pad=0.
// Gather formulation: each output pixel is covered by at most 2x2 regions
// whose starts are multiples of 32 in [p-63, p] clamped to [0,448]; count
// in {1,2,4} -> exact reciprocal. R11: one thread per 8-float span (an
// 8-aligned span never straddles a 32-boundary, so the covering set is
// uniform across the span), using Blackwell 256-bit vector loads/stores
// (ld.global.nc.v8.f32 / st.global.cs.v8.f32). Same MLP as the best R4
// kernel (<=4 loads/thread) but half the LDG instructions and 2x index
// amortization. Store keeps the streaming (.cs) hint.

#define RI_B   4
#define RI_N   225
#define RI_C   16
#define RI_HW  512
#define RI_W8  64   // 512 / 8

__device__ __forceinline__ void ldg256_nc(const float* p, float* r)
{
    asm("ld.global.nc.v8.f32 {%0,%1,%2,%3,%4,%5,%6,%7}, [%8];"
        : "=f"(r[0]), "=f"(r[1]), "=f"(r[2]), "=f"(r[3]),
          "=f"(r[4]), "=f"(r[5]), "=f"(r[6]), "=f"(r[7])
        : "l"(p));
}

__device__ __forceinline__ void stg256_cs(float* p, const float* r)
{
    asm volatile("st.global.cs.v8.f32 [%0], {%1,%2,%3,%4,%5,%6,%7,%8};"
        :: "l"(p),
           "f"(r[0]), "f"(r[1]), "f"(r[2]), "f"(r[3]),
           "f"(r[4]), "f"(r[5]), "f"(r[6]), "f"(r[7])
        : "memory");
}

__global__ __launch_bounds__(256) void region_gather8_kernel(
    const float* __restrict__ regions, float* __restrict__ out)
{
    int idx = blockIdx.x * blockDim.x + threadIdx.x;   // over B*C*H*(W/8) = 2,097,152
    int j8 = (idx & (RI_W8 - 1)) << 3;                 // 0..504, multiple of 8
    int i  = (idx >> 6) & (RI_HW - 1);                 // 0..511
    int bc = idx >> 15;                                 // b*16 + c
    int c  = bc & (RI_C - 1);
    int b  = bc >> 4;

    // Covering row starts: multiples of 32 in [max(0,p-63), min(448,p)]
    int lo_i       = i - 63; if (lo_i < 0) lo_i = 0;
    int hi_i       = i < 448 ? i : 448;
    int s_first_i  = ((lo_i + 31) >> 5) << 5;
    int s_last_i   = (hi_i >> 5) << 5;

    int lo_j       = j8 - 63; if (lo_j < 0) lo_j = 0;
    int hi_j       = j8 < 448 ? j8 : 448;
    int s_first_j  = ((lo_j + 31) >> 5) << 5;
    int s_last_j   = (hi_j >> 5) << 5;

    bool two_i = (s_last_i != s_first_i);
    bool two_j = (s_last_j != s_first_j);

    // regions[((b*225 + n)*16 + c) * 4096 + ri*64 + rj]
    long base_bc = ((long)b * RI_N) * RI_C + c;

    float acc[8];
#pragma unroll
    for (int k = 0; k < 8; k++) acc[k] = 0.f;

    {
        int n  = (s_first_i >> 5) * 15 + (s_first_j >> 5);
        long off = (base_bc + (long)n * RI_C) * 4096 + ((i - s_first_i) << 6) + (j8 - s_first_j);
        float v[8]; ldg256_nc(regions + off, v);
#pragma unroll
        for (int k = 0; k < 8; k++) acc[k] += v[k];
    }
    if (two_j) {
        int n  = (s_first_i >> 5) * 15 + (s_last_j >> 5);
        long off = (base_bc + (long)n * RI_C) * 4096 + ((i - s_first_i) << 6) + (j8 - s_last_j);
        float v[8]; ldg256_nc(regions + off, v);
#pragma unroll
        for (int k = 0; k < 8; k++) acc[k] += v[k];
    }
    if (two_i) {
        int n  = (s_last_i >> 5) * 15 + (s_first_j >> 5);
        long off = (base_bc + (long)n * RI_C) * 4096 + ((i - s_last_i) << 6) + (j8 - s_first_j);
        float v[8]; ldg256_nc(regions + off, v);
#pragma unroll
        for (int k = 0; k < 8; k++) acc[k] += v[k];
    }
    if (two_i && two_j) {
        int n  = (s_last_i >> 5) * 15 + (s_last_j >> 5);
        long off = (base_bc + (long)n * RI_C) * 4096 + ((i - s_last_i) << 6) + (j8 - s_last_j);
        float v[8]; ldg256_nc(regions + off, v);
#pragma unroll
        for (int k = 0; k < 8; k++) acc[k] += v[k];
    }

    int cnt = (two_i ? 2 : 1) * (two_j ? 2 : 1);   // 1, 2 or 4
    float inv = (cnt == 1) ? 1.0f : (cnt == 2 ? 0.5f : 0.25f);
#pragma unroll
    for (int k = 0; k < 8; k++) acc[k] *= inv;

    long oidx = ((long)bc * RI_HW + i) * RI_HW + j8;
    stg256_cs(out + oidx, acc);
}

extern "C" void kernel_launch(void* const* d_in, const int* in_sizes, int n_in,
                              void* d_out, int out_size)
{
    const float* regions = (const float*)d_in[0];
    float* out = (float*)d_out;
    int total = RI_B * RI_C * RI_HW * RI_W8;   // 2,097,152
    int block = 256;
    int grid = total / block;                  // 8192
    region_gather8_kernel<<<grid, block>>>(regions, out);
}